// round 6
// baseline (speedup 1.0000x reference)
#include <cuda_runtime.h>

// ---------------------------------------------------------------------------
// Problem constants (from reference): B=4096, Te=168, Td=24, X=8, H=64
// 3-layer LSTM, gates order i,f,g,o (rows 0:64, 64:128, 128:192, 192:256).
// ---------------------------------------------------------------------------
#define HH      64
#define BT      32          // batch elements per CTA
#define NTHR    256
#define TE      168
#define TD      24
#define XDIM    8
#define BTOT    4096

typedef unsigned long long ull;

// Pre-transposed weights: [(l*128 + j)][h] -> float4 of the 4 gate weights
// (i,f,g,o) for input-dim j, hidden index h. 4 pad row-blocks for prefetch.
__device__ float4 g_W4[(3 * 128 + 4) * 64];

// ---------------------------------------------------------------------------
// f32x2 helpers (packed dual-FMA path; ptxas won't auto-fuse from C++)
// ---------------------------------------------------------------------------
__device__ __forceinline__ ull ffma2(ull a, ull b, ull c) {
    ull d;
    asm("fma.rn.f32x2 %0, %1, %2, %3;" : "=l"(d) : "l"(a), "l"(b), "l"(c));
    return d;
}
__device__ __forceinline__ ull pack2(float lo, float hi) {
    ull d;
    asm("mov.b64 %0, {%1, %2};" : "=l"(d) : "f"(lo), "f"(hi));
    return d;
}
__device__ __forceinline__ float2 unpack2(ull v) {
    float lo, hi;
    asm("mov.b64 {%0, %1}, %2;" : "=f"(lo), "=f"(hi) : "l"(v));
    return make_float2(lo, hi);
}

// sigmoid / tanh via MUFU (ex2.approx + rcp.approx): abs err ~1e-6
__device__ __forceinline__ float fast_sigmoid(float x) {
    float e;
    asm("ex2.approx.f32 %0, %1;" : "=f"(e) : "f"(-1.4426950408889634f * x));
    float r;
    asm("rcp.approx.f32 %0, %1;" : "=f"(r) : "f"(1.0f + e));
    return r;
}
__device__ __forceinline__ float fast_tanh(float x) {
    return fmaf(2.0f, fast_sigmoid(2.0f * x), -1.0f);
}

// ---------------------------------------------------------------------------
// Weight prep: transpose [Wih|Whh] into gate-minor layout g_W4[l][j][h][q].
//   layer0: j<8 -> Wih0[g][j], 8<=j<72 -> Whh0[g][j-8], rest 0
//   layer1/2: j<64 -> Wih[g][j], 64<=j<128 -> Whh[g][j-64]
// ---------------------------------------------------------------------------
__global__ void prep_weights(const float* __restrict__ Wih0, const float* __restrict__ Whh0,
                             const float* __restrict__ Wih1, const float* __restrict__ Whh1,
                             const float* __restrict__ Wih2, const float* __restrict__ Whh2) {
    int idx = blockIdx.x * blockDim.x + threadIdx.x;
    const int total = (3 * 128 + 4) * 64 * 4;
    if (idx >= total) return;
    int q   = idx & 3;
    int lin = idx >> 2;     // float4 index
    int h   = lin & 63;
    int row = lin >> 6;     // l*128 + j  (or pad)
    int l   = row >> 7;
    int j   = row & 127;
    int g   = q * 64 + h;
    float val = 0.0f;
    if (l == 0) {
        if (j < 8)        val = Wih0[g * 8 + j];
        else if (j < 72)  val = Whh0[g * 64 + (j - 8)];
    } else if (l == 1) {
        val = (j < 64) ? Wih1[g * 64 + j] : Whh1[g * 64 + (j - 64)];
    } else if (l == 2) {
        val = (j < 64) ? Wih2[g * 64 + j] : Whh2[g * 64 + (j - 64)];
    }
    reinterpret_cast<float*>(g_W4)[idx] = val;
}

// ---------------------------------------------------------------------------
// Accumulate one input-part into the 4x8 packed-gate accumulators.
//   acc[q][b] : f32x2, .x sums even-j terms, .y sums odd-j terms.
//   wrow0     : first weight row (l*128 + offset)
//   src       : SMEM activations laid out [b][STRIDE], 16B-aligned rows
// Weight loads: 1x LDG.128 per (j), coalesced 512B/warp; next j-block
// prefetched one iteration ahead (pad rows make overrun safe).
// Activation loads: warp-uniform LDS.128 (broadcast, conflict-free).
// ---------------------------------------------------------------------------
template <int WIDTH, int STRIDE>
__device__ __forceinline__ void accum_part(ull acc[4][8], int wrow0, int h,
                                           const float* __restrict__ src, int bs) {
    const float4* __restrict__ wp = g_W4 + (size_t)wrow0 * 64 + h;
    float4 w0 = __ldg(wp + 0);
    float4 w1 = __ldg(wp + 64);
    float4 w2 = __ldg(wp + 128);
    float4 w3 = __ldg(wp + 192);
    const float* sbase = src + bs * STRIDE;
#pragma unroll 2
    for (int j0 = 0; j0 < WIDTH; j0 += 4) {
        // prefetch next j-block (pad rows guarantee in-bounds)
        const float4* np = wp + (size_t)(j0 + 4) * 64;
        float4 n0 = __ldg(np + 0);
        float4 n1 = __ldg(np + 64);
        float4 n2 = __ldg(np + 128);
        float4 n3 = __ldg(np + 192);

        ull pA0 = pack2(w0.x, w1.x), pA1 = pack2(w0.y, w1.y);
        ull pA2 = pack2(w0.z, w1.z), pA3 = pack2(w0.w, w1.w);
        ull pB0 = pack2(w2.x, w3.x), pB1 = pack2(w2.y, w3.y);
        ull pB2 = pack2(w2.z, w3.z), pB3 = pack2(w2.w, w3.w);

#pragma unroll
        for (int b = 0; b < 8; b++) {
            ulonglong2 a = *reinterpret_cast<const ulonglong2*>(sbase + b * STRIDE + j0);
            acc[0][b] = ffma2(pA0, a.x, acc[0][b]);
            acc[1][b] = ffma2(pA1, a.x, acc[1][b]);
            acc[2][b] = ffma2(pA2, a.x, acc[2][b]);
            acc[3][b] = ffma2(pA3, a.x, acc[3][b]);
            acc[0][b] = ffma2(pB0, a.y, acc[0][b]);
            acc[1][b] = ffma2(pB1, a.y, acc[1][b]);
            acc[2][b] = ffma2(pB2, a.y, acc[2][b]);
            acc[3][b] = ffma2(pB3, a.y, acc[3][b]);
        }
        w0 = n0; w1 = n1; w2 = n2; w3 = n3;
    }
}

// One full 3-layer step. Thread t: h = t&63 owns hidden unit h for the
// batch octet bs = (t>>6)*8. Cell state c stays in registers.
__device__ __forceinline__ void step3(float (&c)[3][8], const float (&bias)[3][4],
                                      int h, int bs,
                                      float (*hbuf)[BT][HH], float (*x_s)[XDIM]) {
#pragma unroll
    for (int l = 0; l < 3; l++) {
        ull acc[4][8];
#pragma unroll
        for (int q = 0; q < 4; q++)
#pragma unroll
            for (int k = 0; k < 8; k++) acc[q][k] = pack2(bias[l][q], 0.0f);

        if (l == 0) {
            accum_part<8, XDIM>(acc, 0, h, &x_s[0][0], bs);
            accum_part<64, HH>(acc, 8, h, &hbuf[0][0][0], bs);
        } else if (l == 1) {
            accum_part<64, HH>(acc, 128, h, &hbuf[0][0][0], bs);
            accum_part<64, HH>(acc, 192, h, &hbuf[1][0][0], bs);
        } else {
            accum_part<64, HH>(acc, 256, h, &hbuf[1][0][0], bs);
            accum_part<64, HH>(acc, 320, h, &hbuf[2][0][0], bs);
        }

        float hv[8];
#pragma unroll
        for (int k = 0; k < 8; k++) {
            float2 xi2 = unpack2(acc[0][k]);
            float2 xf2 = unpack2(acc[1][k]);
            float2 xg2 = unpack2(acc[2][k]);
            float2 xo2 = unpack2(acc[3][k]);
            float iv = fast_sigmoid(xi2.x + xi2.y);
            float fv = fast_sigmoid(xf2.x + xf2.y);
            float gv = fast_tanh(xg2.x + xg2.y);
            float ov = fast_sigmoid(xo2.x + xo2.y);
            float cn = fmaf(fv, c[l][k], iv * gv);
            c[l][k]  = cn;
            hv[k]    = ov * fast_tanh(cn);
        }
        __syncthreads();   // all reads of hbuf[l] done before overwrite
#pragma unroll
        for (int k = 0; k < 8; k++) hbuf[l][bs + k][h] = hv[k];
        __syncthreads();   // hbuf[l] visible for next layer / next step
    }
}

// ---------------------------------------------------------------------------
// Main kernel: one CTA per 32-batch tile, full encoder + decoder sequence.
// ---------------------------------------------------------------------------
__global__ void __launch_bounds__(NTHR)
lstm_seq_kernel(const float* __restrict__ enc_x, const float* __restrict__ enc_z,
                const float* __restrict__ dec_x, const float* __restrict__ v,
                const float* __restrict__ eps,
                const float* __restrict__ b0, const float* __restrict__ b1,
                const float* __restrict__ b2,
                const float* __restrict__ w_m, const float* __restrict__ b_m,
                const float* __restrict__ w_a, const float* __restrict__ b_a,
                float* __restrict__ out) {
    __shared__ float hbuf[3][BT][HH];   // [layer][b][h], rows 256B (16B aligned)
    __shared__ float x_s[BT][XDIM];     // current step input, rows 32B
    __shared__ float z_s[BT];
    __shared__ float vf_s[BT];
    __shared__ float rvf_s[BT];
    __shared__ float wm_s[HH];
    __shared__ float wa_s[HH];
    __shared__ float bm_ba[2];

    const int t   = threadIdx.x;
    const int h   = t & 63;
    const int bs  = (t >> 6) * 8;
    const int b0g = blockIdx.x * BT;

    // per-thread gate biases
    float bias[3][4];
#pragma unroll
    for (int q = 0; q < 4; q++) {
        bias[0][q] = b0[q * 64 + h];
        bias[1][q] = b1[q * 64 + h];
        bias[2][q] = b2[q * 64 + h];
    }

    // zero hidden state
    for (int i = t; i < 3 * BT * HH; i += NTHR) (&hbuf[0][0][0])[i] = 0.0f;
    if (t < HH) { wm_s[t] = w_m[t]; wa_s[t] = w_a[t]; }
    if (t == 0) { bm_ba[0] = b_m[0]; bm_ba[1] = b_a[0]; }

    float c[3][8];
#pragma unroll
    for (int l = 0; l < 3; l++)
#pragma unroll
        for (int k = 0; k < 8; k++) c[l][k] = 0.0f;

    const int bb = t >> 3, xi = t & 7;   // 256 threads -> 32x8 x-loader

    // ---------------- encoder ----------------
    for (int s = 0; s < TE; s++) {
        x_s[bb][xi] = enc_x[(size_t)(b0g + bb) * (TE * XDIM) + s * XDIM + xi];
        __syncthreads();
        step3(c, bias, h, bs, hbuf, x_s);
    }

    // ---------------- decoder init ----------------
    if (t < BT) {
        float vf  = v[b0g + t];
        float rvf = 1.0f / vf;
        vf_s[t]  = vf;
        rvf_s[t] = rvf;
        z_s[t]   = enc_z[(size_t)(b0g + t) * TE + (TE - 1)] * rvf;
    }
    __syncthreads();

    // ---------------- decoder ----------------
    for (int s = 0; s < TD; s++) {
        float xv;
        if (xi == 0) xv = z_s[bb];
        else xv = dec_x[(size_t)(b0g + bb) * (TD * (XDIM - 1)) + s * (XDIM - 1) + (xi - 1)];
        x_s[bb][xi] = xv;
        __syncthreads();

        step3(c, bias, h, bs, hbuf, x_s);

        if (t < BT) {
            float m  = bm_ba[0];
            float ap = bm_ba[1];
#pragma unroll
            for (int k = 0; k < HH; k++) {
                float hv = hbuf[2][t][k];
                m  = fmaf(hv, wm_s[k], m);
                ap = fmaf(hv, wa_s[k], ap);
            }
            float vf = vf_s[t];
            m *= vf;
            // stable softplus: max(x,0) + log1p(exp(-|x|))
            float sp = fmaxf(ap, 0.0f) + log1pf(__expf(-fabsf(ap)));
            float a  = sp * vf;
            float zs = fmaf(a, eps[(size_t)(b0g + t) * TD + s], m);
            out[(size_t)(b0g + t) * TD + s] = zs;
            z_s[t] = zs * rvf_s[t];
        }
        __syncthreads();
    }
}

// ---------------------------------------------------------------------------
// Input order (metadata): enc_x, enc_z, dec_x, v, eps,
//   W_ih0, W_hh0, b0, W_ih1, W_hh1, b1, W_ih2, W_hh2, b2, w_m, b_m, w_a, b_a
// ---------------------------------------------------------------------------
extern "C" void kernel_launch(void* const* d_in, const int* in_sizes, int n_in,
                              void* d_out, int out_size) {
    (void)in_sizes; (void)n_in; (void)out_size;
    const float* enc_x = (const float*)d_in[0];
    const float* enc_z = (const float*)d_in[1];
    const float* dec_x = (const float*)d_in[2];
    const float* v     = (const float*)d_in[3];
    const float* eps   = (const float*)d_in[4];
    const float* Wih0  = (const float*)d_in[5];
    const float* Whh0  = (const float*)d_in[6];
    const float* b0    = (const float*)d_in[7];
    const float* Wih1  = (const float*)d_in[8];
    const float* Whh1  = (const float*)d_in[9];
    const float* b1    = (const float*)d_in[10];
    const float* Wih2  = (const float*)d_in[11];
    const float* Whh2  = (const float*)d_in[12];
    const float* b2    = (const float*)d_in[13];
    const float* w_m   = (const float*)d_in[14];
    const float* b_m   = (const float*)d_in[15];
    const float* w_a   = (const float*)d_in[16];
    const float* b_a   = (const float*)d_in[17];
    float* out = (float*)d_out;

    const int total = (3 * 128 + 4) * 64 * 4;
    prep_weights<<<(total + 255) / 256, 256>>>(Wih0, Whh0, Wih1, Whh1, Wih2, Whh2);
    lstm_seq_kernel<<<BTOT / BT, NTHR>>>(enc_x, enc_z, dec_x, v, eps,
                                         b0, b1, b2, w_m, b_m, w_a, b_a, out);
}

// round 7
// speedup vs baseline: 1.8118x; 1.8118x over previous
#include <cuda_runtime.h>

// ---------------------------------------------------------------------------
// B=4096, Te=168, Td=24, X=8, H=64; 3-layer LSTM, gate order i,f,g,o.
// One CTA = 16 batch elements, 256 threads (thread t: h = t&63, owns a
// 4-batch quartet bs=(t>>6)*4 and computes all 4 gates for (h, quartet)).
// grid=256 -> 2 CTAs per SM for latency hiding; cell state in registers.
// ---------------------------------------------------------------------------
#define HH      64
#define BT      16
#define NTHR    256
#define TE      168
#define TD      24
#define XDIM    8
#define BTOT    4096

typedef unsigned long long ull;

// Weight layout: row = l*32 + jb (jb = j/4 within the layer's 128-wide
// concatenated [x|h] input). g_W4[(row*4 + q)*64 + h] = float4 of the 4
// consecutive-j weights for gate q, hidden h. 2 pad rows for prefetch.
#define NROWS   (3 * 32 + 2)
__device__ float4 g_W4[NROWS * 4 * 64];

// ---------------------------------------------------------------------------
// f32x2 dual-FMA (packed path ptxas won't auto-fuse from C++)
// ---------------------------------------------------------------------------
__device__ __forceinline__ ull ffma2(ull a, ull b, ull c) {
    ull d;
    asm("fma.rn.f32x2 %0, %1, %2, %3;" : "=l"(d) : "l"(a), "l"(b), "l"(c));
    return d;
}
__device__ __forceinline__ ull pack2(float lo, float hi) {
    ull d;
    asm("mov.b64 %0, {%1, %2};" : "=l"(d) : "f"(lo), "f"(hi));
    return d;
}
__device__ __forceinline__ float2 unpack2(ull v) {
    float lo, hi;
    asm("mov.b64 {%0, %1}, %2;" : "=f"(lo), "=f"(hi) : "l"(v));
    return make_float2(lo, hi);
}

__device__ __forceinline__ float fast_sigmoid(float x) {
    float e;
    asm("ex2.approx.f32 %0, %1;" : "=f"(e) : "f"(-1.4426950408889634f * x));
    float r;
    asm("rcp.approx.f32 %0, %1;" : "=f"(r) : "f"(1.0f + e));
    return r;
}
__device__ __forceinline__ float fast_tanh(float x) {
    return fmaf(2.0f, fast_sigmoid(2.0f * x), -1.0f);
}

// ---------------------------------------------------------------------------
// Weight prep: g_W4[(row*4+q)*64+h].component[f] = W_l[gate q, h][ j=jb*4+f ]
//   layer0: j<8 -> Wih0, 8<=j<72 -> Whh0 (shifted), else 0
//   layer1/2: j<64 -> Wih, else Whh
// ---------------------------------------------------------------------------
__global__ void prep_weights(const float* __restrict__ Wih0, const float* __restrict__ Whh0,
                             const float* __restrict__ Wih1, const float* __restrict__ Whh1,
                             const float* __restrict__ Wih2, const float* __restrict__ Whh2) {
    int idx = blockIdx.x * blockDim.x + threadIdx.x;
    const int total = NROWS * 4 * 64 * 4;
    if (idx >= total) return;
    int f   = idx & 3;
    int h   = (idx >> 2) & 63;
    int q   = (idx >> 8) & 3;
    int row = idx >> 10;
    int l   = row >> 5;
    int jb  = row & 31;
    int j   = jb * 4 + f;
    int g   = q * 64 + h;
    float val = 0.0f;
    if (l == 0) {
        if (j < 8)       val = Wih0[g * 8 + j];
        else if (j < 72) val = Whh0[g * 64 + (j - 8)];
    } else if (l == 1) {
        val = (j < 64) ? Wih1[g * 64 + j] : Whh1[g * 64 + (j - 64)];
    } else if (l == 2) {
        val = (j < 64) ? Wih2[g * 64 + j] : Whh2[g * 64 + (j - 64)];
    } // l==3 -> pad rows, 0
    reinterpret_cast<float*>(g_W4)[idx] = val;
}

// ---------------------------------------------------------------------------
// Accumulate NBLK 4-j blocks into acc[gate][b] (f32x2: lo/hi sum j-pairs).
// Weights: 4x LDG.128 per block, one-block prefetch (pad rows protect end).
// Activations: warp-uniform (broadcast) LDS.128; register-pair halves are
// the f32x2 operands directly -> zero packing MOVs.
// ---------------------------------------------------------------------------
template <int NBLK, int STRIDE>
__device__ __forceinline__ void accum_part(ull acc[4][4], const float4* __restrict__ wp,
                                           const float* __restrict__ sbase) {
    float4 w0 = __ldg(wp + 0);
    float4 w1 = __ldg(wp + 64);
    float4 w2 = __ldg(wp + 128);
    float4 w3 = __ldg(wp + 192);
#pragma unroll 2
    for (int blk = 0; blk < NBLK; blk++) {
        const float4* np = wp + (blk + 1) * 256;
        float4 n0 = __ldg(np + 0);
        float4 n1 = __ldg(np + 64);
        float4 n2 = __ldg(np + 128);
        float4 n3 = __ldg(np + 192);

        ulonglong2 u0 = *reinterpret_cast<const ulonglong2*>(&w0);
        ulonglong2 u1 = *reinterpret_cast<const ulonglong2*>(&w1);
        ulonglong2 u2 = *reinterpret_cast<const ulonglong2*>(&w2);
        ulonglong2 u3 = *reinterpret_cast<const ulonglong2*>(&w3);
        const float* sp = sbase + blk * 4;
#pragma unroll
        for (int b = 0; b < 4; b++) {
            ulonglong2 a = *reinterpret_cast<const ulonglong2*>(sp + b * STRIDE);
            acc[0][b] = ffma2(u0.x, a.x, acc[0][b]);
            acc[1][b] = ffma2(u1.x, a.x, acc[1][b]);
            acc[2][b] = ffma2(u2.x, a.x, acc[2][b]);
            acc[3][b] = ffma2(u3.x, a.x, acc[3][b]);
            acc[0][b] = ffma2(u0.y, a.y, acc[0][b]);
            acc[1][b] = ffma2(u1.y, a.y, acc[1][b]);
            acc[2][b] = ffma2(u2.y, a.y, acc[2][b]);
            acc[3][b] = ffma2(u3.y, a.y, acc[3][b]);
        }
        w0 = n0; w1 = n1; w2 = n2; w3 = n3;
    }
}

// One 3-layer step with double-buffered hidden state (1 bar per layer).
// Reads hb[l][pp] (prev step), writes hb[l][pp^1].
__device__ __forceinline__ void step3(float (&c)[3][4], const float (&bias)[3][4],
                                      int h, int bs, int pp,
                                      float (*hb)[2][BT][HH],
                                      const float (*x_s)[XDIM]) {
#pragma unroll
    for (int l = 0; l < 3; l++) {
        ull acc[4][4];
#pragma unroll
        for (int q = 0; q < 4; q++)
#pragma unroll
            for (int k = 0; k < 4; k++) acc[q][k] = pack2(bias[l][q], 0.0f);

        if (l == 0) {
            accum_part<2,  XDIM>(acc, g_W4 + 0 * 256 + h,  &x_s[bs][0]);
            accum_part<16, HH  >(acc, g_W4 + 2 * 256 + h,  &hb[0][pp][bs][0]);
        } else if (l == 1) {
            accum_part<16, HH  >(acc, g_W4 + 32 * 256 + h, &hb[0][pp ^ 1][bs][0]);
            accum_part<16, HH  >(acc, g_W4 + 48 * 256 + h, &hb[1][pp][bs][0]);
        } else {
            accum_part<16, HH  >(acc, g_W4 + 64 * 256 + h, &hb[1][pp ^ 1][bs][0]);
            accum_part<16, HH  >(acc, g_W4 + 80 * 256 + h, &hb[2][pp][bs][0]);
        }

        float hv[4];
#pragma unroll
        for (int k = 0; k < 4; k++) {
            float2 xi2 = unpack2(acc[0][k]);
            float2 xf2 = unpack2(acc[1][k]);
            float2 xg2 = unpack2(acc[2][k]);
            float2 xo2 = unpack2(acc[3][k]);
            float iv = fast_sigmoid(xi2.x + xi2.y);
            float fv = fast_sigmoid(xf2.x + xf2.y);
            float gv = fast_tanh(xg2.x + xg2.y);
            float ov = fast_sigmoid(xo2.x + xo2.y);
            float cn = fmaf(fv, c[l][k], iv * gv);
            c[l][k]  = cn;
            hv[k]    = ov * fast_tanh(cn);
        }
#pragma unroll
        for (int k = 0; k < 4; k++) hb[l][pp ^ 1][bs + k][h] = hv[k];
        __syncthreads();   // layer-l outputs visible; old buffer free
    }
}

// ---------------------------------------------------------------------------
// Main kernel: one CTA per 16-batch tile, whole encoder+decoder sequence.
// ---------------------------------------------------------------------------
__global__ void __launch_bounds__(NTHR, 2)
lstm_seq_kernel(const float* __restrict__ enc_x, const float* __restrict__ enc_z,
                const float* __restrict__ dec_x, const float* __restrict__ v,
                const float* __restrict__ eps,
                const float* __restrict__ b0, const float* __restrict__ b1,
                const float* __restrict__ b2,
                const float* __restrict__ w_m, const float* __restrict__ b_m,
                const float* __restrict__ w_a, const float* __restrict__ b_a,
                float* __restrict__ out) {
    __shared__ __align__(16) float hbuf[3][2][BT][HH];   // double-buffered
    __shared__ __align__(16) float x_s[BT][XDIM];
    __shared__ float z_s[BT];
    __shared__ float vf_s[BT];
    __shared__ float rvf_s[BT];
    __shared__ float wm_s[HH];
    __shared__ float wa_s[HH];
    __shared__ float bm_ba[2];

    const int t   = threadIdx.x;
    const int h   = t & 63;
    const int bs  = (t >> 6) * 4;
    const int b0g = blockIdx.x * BT;

    float bias[3][4];
#pragma unroll
    for (int q = 0; q < 4; q++) {
        bias[0][q] = b0[q * 64 + h];
        bias[1][q] = b1[q * 64 + h];
        bias[2][q] = b2[q * 64 + h];
    }

    for (int i = t; i < 3 * 2 * BT * HH; i += NTHR) (&hbuf[0][0][0][0])[i] = 0.0f;
    if (t < HH) { wm_s[t] = w_m[t]; wa_s[t] = w_a[t]; }
    if (t == 0) { bm_ba[0] = b_m[0]; bm_ba[1] = b_a[0]; }

    float c[3][4];
#pragma unroll
    for (int l = 0; l < 3; l++)
#pragma unroll
        for (int k = 0; k < 4; k++) c[l][k] = 0.0f;

    const int bb = t >> 3, xi = t & 7;   // first 128 threads: 16x8 x-loader
    int pp = 0;

    // ---------------- encoder ----------------
    for (int s = 0; s < TE; s++) {
        if (t < BT * XDIM)
            x_s[bb][xi] = enc_x[(size_t)(b0g + bb) * (TE * XDIM) + s * XDIM + xi];
        __syncthreads();
        step3(c, bias, h, bs, pp, hbuf, x_s);
        pp ^= 1;
    }

    // ---------------- decoder init ----------------
    if (t < BT) {
        float vf  = v[b0g + t];
        float rvf = 1.0f / vf;
        vf_s[t]  = vf;
        rvf_s[t] = rvf;
        z_s[t]   = enc_z[(size_t)(b0g + t) * TE + (TE - 1)] * rvf;
    }
    __syncthreads();

    // ---------------- decoder ----------------
    for (int s = 0; s < TD; s++) {
        if (t < BT * XDIM) {
            float xv;
            if (xi == 0) xv = z_s[bb];
            else xv = dec_x[(size_t)(b0g + bb) * (TD * (XDIM - 1)) + s * (XDIM - 1) + (xi - 1)];
            x_s[bb][xi] = xv;
        }
        __syncthreads();

        step3(c, bias, h, bs, pp, hbuf, x_s);

        if (t < BT) {
            float m  = bm_ba[0];
            float ap = bm_ba[1];
            const float* hrow = &hbuf[2][pp ^ 1][t][0];
#pragma unroll
            for (int kk = 0; kk < HH; kk++) {
                int k = (kk + t) & 63;       // bank-conflict-free rotation
                float hv = hrow[k];
                m  = fmaf(hv, wm_s[k], m);
                ap = fmaf(hv, wa_s[k], ap);
            }
            float vf = vf_s[t];
            m *= vf;
            float sp = fmaxf(ap, 0.0f) + log1pf(__expf(-fabsf(ap)));
            float a  = sp * vf;
            float zs = fmaf(a, eps[(size_t)(b0g + t) * TD + s], m);
            out[(size_t)(b0g + t) * TD + s] = zs;
            z_s[t] = zs * rvf_s[t];
        }
        pp ^= 1;
        __syncthreads();   // z_s ready before next step's loader reads it
    }
}

// ---------------------------------------------------------------------------
// Input order: enc_x, enc_z, dec_x, v, eps,
//   W_ih0, W_hh0, b0, W_ih1, W_hh1, b1, W_ih2, W_hh2, b2, w_m, b_m, w_a, b_a
// ---------------------------------------------------------------------------
extern "C" void kernel_launch(void* const* d_in, const int* in_sizes, int n_in,
                              void* d_out, int out_size) {
    (void)in_sizes; (void)n_in; (void)out_size;
    const float* enc_x = (const float*)d_in[0];
    const float* enc_z = (const float*)d_in[1];
    const float* dec_x = (const float*)d_in[2];
    const float* v     = (const float*)d_in[3];
    const float* eps   = (const float*)d_in[4];
    const float* Wih0  = (const float*)d_in[5];
    const float* Whh0  = (const float*)d_in[6];
    const float* b0    = (const float*)d_in[7];
    const float* Wih1  = (const float*)d_in[8];
    const float* Whh1  = (const float*)d_in[9];
    const float* b1    = (const float*)d_in[10];
    const float* Wih2  = (const float*)d_in[11];
    const float* Whh2  = (const float*)d_in[12];
    const float* b2    = (const float*)d_in[13];
    const float* w_m   = (const float*)d_in[14];
    const float* b_m   = (const float*)d_in[15];
    const float* w_a   = (const float*)d_in[16];
    const float* b_a   = (const float*)d_in[17];
    float* out = (float*)d_out;

    const int total = NROWS * 4 * 64 * 4;
    prep_weights<<<(total + 255) / 256, 256>>>(Wih0, Whh0, Wih1, Whh1, Wih2, Whh2);
    lstm_seq_kernel<<<BTOT / BT, NTHR>>>(enc_x, enc_z, dec_x, v, eps,
                                         b0, b1, b2, w_m, b_m, w_a, b_a, out);
}

// round 8
// speedup vs baseline: 1.9305x; 1.0655x over previous
#include <cuda_runtime.h>

// ---------------------------------------------------------------------------
// B=4096, Te=168, Td=24, X=8, H=64; 3-layer LSTM, gate order i,f,g,o.
// One CTA = 16 batch elements, 128 threads. Thread t: h = t&63, owns an
// 8-batch slice bs=(t>>6)*8 and computes all 4 gates for (h, slice).
// grid=256, 2 CTAs/SM. Cell state in registers; h state in SMEM (double buf).
// ---------------------------------------------------------------------------
#define HH      64
#define BT      16
#define NTHR    128
#define TE      168
#define TD      24
#define XDIM    8
#define BTOT    4096

typedef unsigned long long ull;

// Weight layout: row = l*32 + jb (jb = j/4 within the layer's 128-wide
// concatenated [x|h] input). g_W4[(row*4 + q)*64 + h] = float4 of the 4
// consecutive-j weights for gate q, hidden h. 2 pad rows for prefetch.
#define NROWS   (3 * 32 + 2)
__device__ float4 g_W4[NROWS * 4 * 64];

// ---------------------------------------------------------------------------
// f32x2 dual-FMA (packed path ptxas won't auto-fuse from C++)
// ---------------------------------------------------------------------------
__device__ __forceinline__ ull ffma2(ull a, ull b, ull c) {
    ull d;
    asm("fma.rn.f32x2 %0, %1, %2, %3;" : "=l"(d) : "l"(a), "l"(b), "l"(c));
    return d;
}
__device__ __forceinline__ ull pack2(float lo, float hi) {
    ull d;
    asm("mov.b64 %0, {%1, %2};" : "=l"(d) : "f"(lo), "f"(hi));
    return d;
}
__device__ __forceinline__ float2 unpack2(ull v) {
    float lo, hi;
    asm("mov.b64 {%0, %1}, %2;" : "=f"(lo), "=f"(hi) : "l"(v));
    return make_float2(lo, hi);
}

__device__ __forceinline__ float fast_sigmoid(float x) {
    float e;
    asm("ex2.approx.f32 %0, %1;" : "=f"(e) : "f"(-1.4426950408889634f * x));
    float r;
    asm("rcp.approx.f32 %0, %1;" : "=f"(r) : "f"(1.0f + e));
    return r;
}
__device__ __forceinline__ float fast_tanh(float x) {
    return fmaf(2.0f, fast_sigmoid(2.0f * x), -1.0f);
}

// ---------------------------------------------------------------------------
// Weight prep: g_W4[(row*4+q)*64+h].component[f] = W_l[gate q, h][ j=jb*4+f ]
// ---------------------------------------------------------------------------
__global__ void prep_weights(const float* __restrict__ Wih0, const float* __restrict__ Whh0,
                             const float* __restrict__ Wih1, const float* __restrict__ Whh1,
                             const float* __restrict__ Wih2, const float* __restrict__ Whh2) {
    int idx = blockIdx.x * blockDim.x + threadIdx.x;
    const int total = NROWS * 4 * 64 * 4;
    if (idx >= total) return;
    int f   = idx & 3;
    int h   = (idx >> 2) & 63;
    int q   = (idx >> 8) & 3;
    int row = idx >> 10;
    int l   = row >> 5;
    int jb  = row & 31;
    int j   = jb * 4 + f;
    int g   = q * 64 + h;
    float val = 0.0f;
    if (l == 0) {
        if (j < 8)       val = Wih0[g * 8 + j];
        else if (j < 72) val = Whh0[g * 64 + (j - 8)];
    } else if (l == 1) {
        val = (j < 64) ? Wih1[g * 64 + j] : Whh1[g * 64 + (j - 64)];
    } else if (l == 2) {
        val = (j < 64) ? Wih2[g * 64 + j] : Whh2[g * 64 + (j - 64)];
    } // pad rows -> 0
    reinterpret_cast<float*>(g_W4)[idx] = val;
}

// ---------------------------------------------------------------------------
// Accumulate NBLK 4-j blocks into acc[gate][b], b in 0..7 (f32x2 lanes sum
// even/odd j). Weights: 4x LDG.128 per block with one-block prefetch
// (pad rows protect the overrun). Activations: warp-uniform LDS.128.
// Per block: 16 weight wf + 8 act wf feed 64 FFMA2.
// ---------------------------------------------------------------------------
template <int NBLK, int STRIDE>
__device__ __forceinline__ void accum_part(ull acc[4][8], const float4* __restrict__ wp,
                                           const float* __restrict__ sbase) {
    float4 w0 = __ldg(wp + 0);
    float4 w1 = __ldg(wp + 64);
    float4 w2 = __ldg(wp + 128);
    float4 w3 = __ldg(wp + 192);
#pragma unroll 2
    for (int blk = 0; blk < NBLK; blk++) {
        const float4* np = wp + (blk + 1) * 256;
        float4 n0 = __ldg(np + 0);
        float4 n1 = __ldg(np + 64);
        float4 n2 = __ldg(np + 128);
        float4 n3 = __ldg(np + 192);

        ulonglong2 u0 = *reinterpret_cast<const ulonglong2*>(&w0);
        ulonglong2 u1 = *reinterpret_cast<const ulonglong2*>(&w1);
        ulonglong2 u2 = *reinterpret_cast<const ulonglong2*>(&w2);
        ulonglong2 u3 = *reinterpret_cast<const ulonglong2*>(&w3);
        const float* sp = sbase + blk * 4;
#pragma unroll
        for (int b = 0; b < 8; b++) {
            ulonglong2 a = *reinterpret_cast<const ulonglong2*>(sp + b * STRIDE);
            acc[0][b] = ffma2(u0.x, a.x, acc[0][b]);
            acc[1][b] = ffma2(u1.x, a.x, acc[1][b]);
            acc[2][b] = ffma2(u2.x, a.x, acc[2][b]);
            acc[3][b] = ffma2(u3.x, a.x, acc[3][b]);
            acc[0][b] = ffma2(u0.y, a.y, acc[0][b]);
            acc[1][b] = ffma2(u1.y, a.y, acc[1][b]);
            acc[2][b] = ffma2(u2.y, a.y, acc[2][b]);
            acc[3][b] = ffma2(u3.y, a.y, acc[3][b]);
        }
        w0 = n0; w1 = n1; w2 = n2; w3 = n3;
    }
}

// One 3-layer step with double-buffered hidden state (1 bar per layer).
// Reads hb[l][pp] (prev step), writes hb[l][pp^1].
__device__ __forceinline__ void step3(float (&c)[3][8], const float (&bias)[3][4],
                                      int h, int bs, int pp,
                                      float (*hb)[2][BT][HH],
                                      const float (*x_s)[XDIM]) {
#pragma unroll
    for (int l = 0; l < 3; l++) {
        ull acc[4][8];
#pragma unroll
        for (int q = 0; q < 4; q++)
#pragma unroll
            for (int k = 0; k < 8; k++) acc[q][k] = pack2(bias[l][q], 0.0f);

        if (l == 0) {
            accum_part<2,  XDIM>(acc, g_W4 + 0 * 256 + h,  &x_s[bs][0]);
            accum_part<16, HH  >(acc, g_W4 + 2 * 256 + h,  &hb[0][pp][bs][0]);
        } else if (l == 1) {
            accum_part<16, HH  >(acc, g_W4 + 32 * 256 + h, &hb[0][pp ^ 1][bs][0]);
            accum_part<16, HH  >(acc, g_W4 + 48 * 256 + h, &hb[1][pp][bs][0]);
        } else {
            accum_part<16, HH  >(acc, g_W4 + 64 * 256 + h, &hb[1][pp ^ 1][bs][0]);
            accum_part<16, HH  >(acc, g_W4 + 80 * 256 + h, &hb[2][pp][bs][0]);
        }

        float hv[8];
#pragma unroll
        for (int k = 0; k < 8; k++) {
            float2 xi2 = unpack2(acc[0][k]);
            float2 xf2 = unpack2(acc[1][k]);
            float2 xg2 = unpack2(acc[2][k]);
            float2 xo2 = unpack2(acc[3][k]);
            float iv = fast_sigmoid(xi2.x + xi2.y);
            float fv = fast_sigmoid(xf2.x + xf2.y);
            float gv = fast_tanh(xg2.x + xg2.y);
            float ov = fast_sigmoid(xo2.x + xo2.y);
            float cn = fmaf(fv, c[l][k], iv * gv);
            c[l][k]  = cn;
            hv[k]    = ov * fast_tanh(cn);
        }
#pragma unroll
        for (int k = 0; k < 8; k++) hb[l][pp ^ 1][bs + k][h] = hv[k];
        __syncthreads();   // layer-l outputs visible; old buffer free
    }
}

// ---------------------------------------------------------------------------
// Main kernel: one CTA per 16-batch tile, whole encoder+decoder sequence.
// ---------------------------------------------------------------------------
__global__ void __launch_bounds__(NTHR, 2)
lstm_seq_kernel(const float* __restrict__ enc_x, const float* __restrict__ enc_z,
                const float* __restrict__ dec_x, const float* __restrict__ v,
                const float* __restrict__ eps,
                const float* __restrict__ b0, const float* __restrict__ b1,
                const float* __restrict__ b2,
                const float* __restrict__ w_m, const float* __restrict__ b_m,
                const float* __restrict__ w_a, const float* __restrict__ b_a,
                float* __restrict__ out) {
    __shared__ __align__(16) float hbuf[3][2][BT][HH];   // double-buffered
    __shared__ __align__(16) float x_s[BT][XDIM];
    __shared__ float z_s[BT];
    __shared__ float vf_s[BT];
    __shared__ float rvf_s[BT];
    __shared__ float wm_s[HH];
    __shared__ float wa_s[HH];
    __shared__ float bm_ba[2];

    const int t   = threadIdx.x;
    const int h   = t & 63;
    const int bs  = (t >> 6) * 8;    // 2 groups x 8 batches = 16
    const int b0g = blockIdx.x * BT;

    float bias[3][4];
#pragma unroll
    for (int q = 0; q < 4; q++) {
        bias[0][q] = b0[q * 64 + h];
        bias[1][q] = b1[q * 64 + h];
        bias[2][q] = b2[q * 64 + h];
    }

    for (int i = t; i < 3 * 2 * BT * HH; i += NTHR) (&hbuf[0][0][0][0])[i] = 0.0f;
    if (t < HH) { wm_s[t] = w_m[t]; wa_s[t] = w_a[t]; }
    if (t == 0) { bm_ba[0] = b_m[0]; bm_ba[1] = b_a[0]; }

    float c[3][8];
#pragma unroll
    for (int l = 0; l < 3; l++)
#pragma unroll
        for (int k = 0; k < 8; k++) c[l][k] = 0.0f;

    const int bb = t >> 3, xi = t & 7;   // 128 threads: 16x8 x-loader
    int pp = 0;

    // ---------------- encoder ----------------
    for (int s = 0; s < TE; s++) {
        x_s[bb][xi] = enc_x[(size_t)(b0g + bb) * (TE * XDIM) + s * XDIM + xi];
        __syncthreads();
        step3(c, bias, h, bs, pp, hbuf, x_s);
        pp ^= 1;
    }

    // ---------------- decoder init ----------------
    if (t < BT) {
        float vf  = v[b0g + t];
        float rvf = 1.0f / vf;
        vf_s[t]  = vf;
        rvf_s[t] = rvf;
        z_s[t]   = enc_z[(size_t)(b0g + t) * TE + (TE - 1)] * rvf;
    }
    __syncthreads();

    // ---------------- decoder ----------------
    for (int s = 0; s < TD; s++) {
        {
            float xv;
            if (xi == 0) xv = z_s[bb];
            else xv = dec_x[(size_t)(b0g + bb) * (TD * (XDIM - 1)) + s * (XDIM - 1) + (xi - 1)];
            x_s[bb][xi] = xv;
        }
        __syncthreads();

        step3(c, bias, h, bs, pp, hbuf, x_s);

        if (t < BT) {
            float m  = bm_ba[0];
            float ap = bm_ba[1];
            const float* hrow = &hbuf[2][pp ^ 1][t][0];
#pragma unroll
            for (int kk = 0; kk < HH; kk++) {
                int k = (kk + t) & 63;       // bank-conflict-free rotation
                float hv = hrow[k];
                m  = fmaf(hv, wm_s[k], m);
                ap = fmaf(hv, wa_s[k], ap);
            }
            float vf = vf_s[t];
            m *= vf;
            float sp = fmaxf(ap, 0.0f) + log1pf(__expf(-fabsf(ap)));
            float a  = sp * vf;
            float zs = fmaf(a, eps[(size_t)(b0g + t) * TD + s], m);
            out[(size_t)(b0g + t) * TD + s] = zs;
            z_s[t] = zs * rvf_s[t];
        }
        pp ^= 1;
        __syncthreads();   // z_s ready before next step's loader reads it
    }
}

// ---------------------------------------------------------------------------
// Input order: enc_x, enc_z, dec_x, v, eps,
//   W_ih0, W_hh0, b0, W_ih1, W_hh1, b1, W_ih2, W_hh2, b2, w_m, b_m, w_a, b_a
// ---------------------------------------------------------------------------
extern "C" void kernel_launch(void* const* d_in, const int* in_sizes, int n_in,
                              void* d_out, int out_size) {
    (void)in_sizes; (void)n_in; (void)out_size;
    const float* enc_x = (const float*)d_in[0];
    const float* enc_z = (const float*)d_in[1];
    const float* dec_x = (const float*)d_in[2];
    const float* v     = (const float*)d_in[3];
    const float* eps   = (const float*)d_in[4];
    const float* Wih0  = (const float*)d_in[5];
    const float* Whh0  = (const float*)d_in[6];
    const float* b0    = (const float*)d_in[7];
    const float* Wih1  = (const float*)d_in[8];
    const float* Whh1  = (const float*)d_in[9];
    const float* b1    = (const float*)d_in[10];
    const float* Wih2  = (const float*)d_in[11];
    const float* Whh2  = (const float*)d_in[12];
    const float* b2    = (const float*)d_in[13];
    const float* w_m   = (const float*)d_in[14];
    const float* b_m   = (const float*)d_in[15];
    const float* w_a   = (const float*)d_in[16];
    const float* b_a   = (const float*)d_in[17];
    float* out = (float*)d_out;

    const int total = NROWS * 4 * 64 * 4;
    prep_weights<<<(total + 255) / 256, 256>>>(Wih0, Whh0, Wih1, Whh1, Wih2, Whh2);
    lstm_seq_kernel<<<BTOT / BT, NTHR>>>(enc_x, enc_z, dec_x, v, eps,
                                         b0, b1, b2, w_m, b_m, w_a, b_a, out);
}

// round 9
// speedup vs baseline: 1.9862x; 1.0289x over previous
#include <cuda_runtime.h>

// ---------------------------------------------------------------------------
// B=4096, Te=168, Td=24, X=8, H=64; 3-layer LSTM, gate order i,f,g,o.
// One CTA = 32 batch elements, 256 threads (8 warps, barrier-convoyed so
// they share the weight stream in L1). Thread t: h = t&63, owns an 8-batch
// slice bs=(t>>6)*8, computes all 4 gates for (h, slice). grid=128 -> one
// CTA per SM. Cell state in registers; h state double-buffered in SMEM.
// ---------------------------------------------------------------------------
#define HH      64
#define BT      32
#define NTHR    256
#define TE      168
#define TD      24
#define XDIM    8
#define BTOT    4096

typedef unsigned long long ull;

// Weight layout: row = l*32 + jb (jb = j/4 within the layer's 128-wide
// concatenated [x|h] input). g_W4[(row*4 + q)*64 + h] = float4 of the 4
// consecutive-j weights for gate q, hidden h. 2 pad rows for prefetch.
#define NROWS   (3 * 32 + 2)
__device__ float4 g_W4[NROWS * 4 * 64];

// ---------------------------------------------------------------------------
// f32x2 dual-FMA (packed path ptxas won't auto-fuse from C++)
// ---------------------------------------------------------------------------
__device__ __forceinline__ ull ffma2(ull a, ull b, ull c) {
    ull d;
    asm("fma.rn.f32x2 %0, %1, %2, %3;" : "=l"(d) : "l"(a), "l"(b), "l"(c));
    return d;
}
__device__ __forceinline__ ull pack2(float lo, float hi) {
    ull d;
    asm("mov.b64 %0, {%1, %2};" : "=l"(d) : "f"(lo), "f"(hi));
    return d;
}
__device__ __forceinline__ float2 unpack2(ull v) {
    float lo, hi;
    asm("mov.b64 {%0, %1}, %2;" : "=f"(lo), "=f"(hi) : "l"(v));
    return make_float2(lo, hi);
}

__device__ __forceinline__ float fast_sigmoid(float x) {
    float e;
    asm("ex2.approx.f32 %0, %1;" : "=f"(e) : "f"(-1.4426950408889634f * x));
    float r;
    asm("rcp.approx.f32 %0, %1;" : "=f"(r) : "f"(1.0f + e));
    return r;
}
__device__ __forceinline__ float fast_tanh(float x) {
    return fmaf(2.0f, fast_sigmoid(2.0f * x), -1.0f);
}

// ---------------------------------------------------------------------------
// Weight prep: g_W4[(row*4+q)*64+h].component[f] = W_l[gate q, h][ j=jb*4+f ]
// ---------------------------------------------------------------------------
__global__ void prep_weights(const float* __restrict__ Wih0, const float* __restrict__ Whh0,
                             const float* __restrict__ Wih1, const float* __restrict__ Whh1,
                             const float* __restrict__ Wih2, const float* __restrict__ Whh2) {
    int idx = blockIdx.x * blockDim.x + threadIdx.x;
    const int total = NROWS * 4 * 64 * 4;
    if (idx >= total) return;
    int f   = idx & 3;
    int h   = (idx >> 2) & 63;
    int q   = (idx >> 8) & 3;
    int row = idx >> 10;
    int l   = row >> 5;
    int jb  = row & 31;
    int j   = jb * 4 + f;
    int g   = q * 64 + h;
    float val = 0.0f;
    if (l == 0) {
        if (j < 8)       val = Wih0[g * 8 + j];
        else if (j < 72) val = Whh0[g * 64 + (j - 8)];
    } else if (l == 1) {
        val = (j < 64) ? Wih1[g * 64 + j] : Whh1[g * 64 + (j - 64)];
    } else if (l == 2) {
        val = (j < 64) ? Wih2[g * 64 + j] : Whh2[g * 64 + (j - 64)];
    } // pad rows -> 0
    reinterpret_cast<float*>(g_W4)[idx] = val;
}

// ---------------------------------------------------------------------------
// Accumulate NBLK 4-j blocks into acc[gate][b], b in 0..7 (f32x2 lanes sum
// even/odd j). Weights: 4x LDG.128 per block with one-block prefetch
// (pad rows protect the overrun). Activations: warp-uniform LDS.128.
// ---------------------------------------------------------------------------
template <int NBLK, int STRIDE>
__device__ __forceinline__ void accum_part(ull acc[4][8], const float4* __restrict__ wp,
                                           const float* __restrict__ sbase) {
    float4 w0 = __ldg(wp + 0);
    float4 w1 = __ldg(wp + 64);
    float4 w2 = __ldg(wp + 128);
    float4 w3 = __ldg(wp + 192);
#pragma unroll 2
    for (int blk = 0; blk < NBLK; blk++) {
        const float4* np = wp + (blk + 1) * 256;
        float4 n0 = __ldg(np + 0);
        float4 n1 = __ldg(np + 64);
        float4 n2 = __ldg(np + 128);
        float4 n3 = __ldg(np + 192);

        ulonglong2 u0 = *reinterpret_cast<const ulonglong2*>(&w0);
        ulonglong2 u1 = *reinterpret_cast<const ulonglong2*>(&w1);
        ulonglong2 u2 = *reinterpret_cast<const ulonglong2*>(&w2);
        ulonglong2 u3 = *reinterpret_cast<const ulonglong2*>(&w3);
        const float* sp = sbase + blk * 4;
#pragma unroll
        for (int b = 0; b < 8; b++) {
            ulonglong2 a = *reinterpret_cast<const ulonglong2*>(sp + b * STRIDE);
            acc[0][b] = ffma2(u0.x, a.x, acc[0][b]);
            acc[1][b] = ffma2(u1.x, a.x, acc[1][b]);
            acc[2][b] = ffma2(u2.x, a.x, acc[2][b]);
            acc[3][b] = ffma2(u3.x, a.x, acc[3][b]);
            acc[0][b] = ffma2(u0.y, a.y, acc[0][b]);
            acc[1][b] = ffma2(u1.y, a.y, acc[1][b]);
            acc[2][b] = ffma2(u2.y, a.y, acc[2][b]);
            acc[3][b] = ffma2(u3.y, a.y, acc[3][b]);
        }
        w0 = n0; w1 = n1; w2 = n2; w3 = n3;
    }
}

// Dynamic SMEM layout (exceeds 48KB static limit)
struct Smem {
    float hbuf[3][2][BT][HH];   // double-buffered hidden state (48 KB)
    float x_s[2][BT][XDIM];     // double-buffered step input
    float z_s[BT];
    float vf_s[BT];
    float rvf_s[BT];
    float wm_s[HH];
    float wa_s[HH];
    float bm_ba[2];
};

// One 3-layer step with double-buffered hidden state (1 bar per layer).
// Reads hb[l][pp] (prev step), writes hb[l][pp^1].
__device__ __forceinline__ void step3(float (&c)[3][8], const float (&bias)[3][4],
                                      int h, int bs, int pp,
                                      float (*hb)[2][BT][HH],
                                      const float (*x_s)[XDIM]) {
#pragma unroll
    for (int l = 0; l < 3; l++) {
        ull acc[4][8];
#pragma unroll
        for (int q = 0; q < 4; q++)
#pragma unroll
            for (int k = 0; k < 8; k++) acc[q][k] = pack2(bias[l][q], 0.0f);

        if (l == 0) {
            accum_part<2,  XDIM>(acc, g_W4 + 0 * 256 + h,  &x_s[bs][0]);
            accum_part<16, HH  >(acc, g_W4 + 2 * 256 + h,  &hb[0][pp][bs][0]);
        } else if (l == 1) {
            accum_part<16, HH  >(acc, g_W4 + 32 * 256 + h, &hb[0][pp ^ 1][bs][0]);
            accum_part<16, HH  >(acc, g_W4 + 48 * 256 + h, &hb[1][pp][bs][0]);
        } else {
            accum_part<16, HH  >(acc, g_W4 + 64 * 256 + h, &hb[1][pp ^ 1][bs][0]);
            accum_part<16, HH  >(acc, g_W4 + 80 * 256 + h, &hb[2][pp][bs][0]);
        }

        float hv[8];
#pragma unroll
        for (int k = 0; k < 8; k++) {
            float2 xi2 = unpack2(acc[0][k]);
            float2 xf2 = unpack2(acc[1][k]);
            float2 xg2 = unpack2(acc[2][k]);
            float2 xo2 = unpack2(acc[3][k]);
            float iv = fast_sigmoid(xi2.x + xi2.y);
            float fv = fast_sigmoid(xf2.x + xf2.y);
            float gv = fast_tanh(xg2.x + xg2.y);
            float ov = fast_sigmoid(xo2.x + xo2.y);
            float cn = fmaf(fv, c[l][k], iv * gv);
            c[l][k]  = cn;
            hv[k]    = ov * fast_tanh(cn);
        }
#pragma unroll
        for (int k = 0; k < 8; k++) hb[l][pp ^ 1][bs + k][h] = hv[k];
        __syncthreads();   // layer-l outputs visible; old buffer free
    }
}

// ---------------------------------------------------------------------------
// Main kernel: one CTA per 32-batch tile, whole encoder+decoder sequence.
// ---------------------------------------------------------------------------
__global__ void __launch_bounds__(NTHR, 1)
lstm_seq_kernel(const float* __restrict__ enc_x, const float* __restrict__ enc_z,
                const float* __restrict__ dec_x, const float* __restrict__ v,
                const float* __restrict__ eps,
                const float* __restrict__ b0, const float* __restrict__ b1,
                const float* __restrict__ b2,
                const float* __restrict__ w_m, const float* __restrict__ b_m,
                const float* __restrict__ w_a, const float* __restrict__ b_a,
                float* __restrict__ out) {
    extern __shared__ __align__(16) char smem_raw[];
    Smem& sm = *reinterpret_cast<Smem*>(smem_raw);

    const int t   = threadIdx.x;
    const int h   = t & 63;
    const int bs  = (t >> 6) * 8;    // 4 groups x 8 batches = 32
    const int b0g = blockIdx.x * BT;

    float bias[3][4];
#pragma unroll
    for (int q = 0; q < 4; q++) {
        bias[0][q] = b0[q * 64 + h];
        bias[1][q] = b1[q * 64 + h];
        bias[2][q] = b2[q * 64 + h];
    }

    for (int i = t; i < 3 * 2 * BT * HH; i += NTHR) (&sm.hbuf[0][0][0][0])[i] = 0.0f;
    if (t < HH) { sm.wm_s[t] = w_m[t]; sm.wa_s[t] = w_a[t]; }
    if (t == 0) { sm.bm_ba[0] = b_m[0]; sm.bm_ba[1] = b_a[0]; }

    float c[3][8];
#pragma unroll
    for (int l = 0; l < 3; l++)
#pragma unroll
        for (int k = 0; k < 8; k++) c[l][k] = 0.0f;

    const int bb = t >> 3, xi = t & 7;   // 256 threads = 32x8 x-loader
    int pp = 0;

    // ---------------- encoder ----------------
    // x double-buffered: load step s+1 under cover of step s's layer barriers.
    sm.x_s[0][bb][xi] = enc_x[(size_t)(b0g + bb) * (TE * XDIM) + 0 * XDIM + xi];
    __syncthreads();
    for (int s = 0; s < TE; s++) {
        int cur = s & 1;
        if (s + 1 < TE)
            sm.x_s[cur ^ 1][bb][xi] =
                enc_x[(size_t)(b0g + bb) * (TE * XDIM) + (s + 1) * XDIM + xi];
        step3(c, bias, h, bs, pp, sm.hbuf, sm.x_s[cur]);
        pp ^= 1;
    }

    // ---------------- decoder init ----------------
    if (t < BT) {
        float vf  = v[b0g + t];
        float rvf = 1.0f / vf;
        sm.vf_s[t]  = vf;
        sm.rvf_s[t] = rvf;
        sm.z_s[t]   = enc_z[(size_t)(b0g + t) * TE + (TE - 1)] * rvf;
    }
    __syncthreads();

    // ---------------- decoder ----------------
    for (int s = 0; s < TD; s++) {
        {
            float xv;
            if (xi == 0) xv = sm.z_s[bb];
            else xv = dec_x[(size_t)(b0g + bb) * (TD * (XDIM - 1)) + s * (XDIM - 1) + (xi - 1)];
            sm.x_s[0][bb][xi] = xv;
        }
        __syncthreads();

        step3(c, bias, h, bs, pp, sm.hbuf, sm.x_s[0]);

        if (t < BT) {
            float m  = sm.bm_ba[0];
            float ap = sm.bm_ba[1];
            const float* hrow = &sm.hbuf[2][pp ^ 1][t][0];
#pragma unroll
            for (int kk = 0; kk < HH; kk++) {
                int k = (kk + t) & 63;       // bank-conflict-free rotation
                float hv = hrow[k];
                m  = fmaf(hv, sm.wm_s[k], m);
                ap = fmaf(hv, sm.wa_s[k], ap);
            }
            float vf = sm.vf_s[t];
            m *= vf;
            float sp = fmaxf(ap, 0.0f) + log1pf(__expf(-fabsf(ap)));
            float a  = sp * vf;
            float zs = fmaf(a, eps[(size_t)(b0g + t) * TD + s], m);
            out[(size_t)(b0g + t) * TD + s] = zs;
            sm.z_s[t] = zs * sm.rvf_s[t];
        }
        pp ^= 1;
        __syncthreads();   // z_s ready before next step's loader reads it
    }
}

// ---------------------------------------------------------------------------
// Input order: enc_x, enc_z, dec_x, v, eps,
//   W_ih0, W_hh0, b0, W_ih1, W_hh1, b1, W_ih2, W_hh2, b2, w_m, b_m, w_a, b_a
// ---------------------------------------------------------------------------
extern "C" void kernel_launch(void* const* d_in, const int* in_sizes, int n_in,
                              void* d_out, int out_size) {
    (void)in_sizes; (void)n_in; (void)out_size;
    const float* enc_x = (const float*)d_in[0];
    const float* enc_z = (const float*)d_in[1];
    const float* dec_x = (const float*)d_in[2];
    const float* v     = (const float*)d_in[3];
    const float* eps   = (const float*)d_in[4];
    const float* Wih0  = (const float*)d_in[5];
    const float* Whh0  = (const float*)d_in[6];
    const float* b0    = (const float*)d_in[7];
    const float* Wih1  = (const float*)d_in[8];
    const float* Whh1  = (const float*)d_in[9];
    const float* b1    = (const float*)d_in[10];
    const float* Wih2  = (const float*)d_in[11];
    const float* Whh2  = (const float*)d_in[12];
    const float* b2    = (const float*)d_in[13];
    const float* w_m   = (const float*)d_in[14];
    const float* b_m   = (const float*)d_in[15];
    const float* w_a   = (const float*)d_in[16];
    const float* b_a   = (const float*)d_in[17];
    float* out = (float*)d_out;

    // >48KB smem: opt in every call (idempotent, not a stream op — capture-safe)
    cudaFuncSetAttribute(lstm_seq_kernel,
                         cudaFuncAttributeMaxDynamicSharedMemorySize,
                         (int)sizeof(Smem));

    const int total = NROWS * 4 * 64 * 4;
    prep_weights<<<(total + 255) / 256, 256>>>(Wih0, Whh0, Wih1, Whh1, Wih2, Whh2);
    lstm_seq_kernel<<<BTOT / BT, NTHR, sizeof(Smem)>>>(enc_x, enc_z, dec_x, v, eps,
                                                       b0, b1, b2, w_m, b_m, w_a, b_a, out);
}

// round 10
// speedup vs baseline: 1.9889x; 1.0014x over previous
#include <cuda_runtime.h>

// ---------------------------------------------------------------------------
// B=4096, Te=168, Td=24, X=8, H=64; 3-layer LSTM, gate order i,f,g,o.
// One CTA = 32 batch elements, 256 threads (8 warps, barrier-convoyed so
// they share the weight stream in L1). Thread t: h = t&63, owns an 8-batch
// slice bs=(t>>6)*8, computes all 4 gates for (h, slice). grid=128 -> one
// CTA per SM. Cell state in registers; h state double-buffered in SMEM.
// ---------------------------------------------------------------------------
#define HH      64
#define BT      32
#define NTHR    256
#define TE      168
#define TD      24
#define XDIM    8
#define BTOT    4096

typedef unsigned long long ull;

// Weight layout: row = l*32 + jb (jb = j/4 within the layer's 128-wide
// concatenated [x|h] input). g_W4[(row*4 + q)*64 + h] = float4 of the 4
// consecutive-j weights for gate q, hidden h. 2 pad rows for prefetch.
#define NROWS   (3 * 32 + 2)
__device__ float4 g_W4[NROWS * 4 * 64];

// ---------------------------------------------------------------------------
// f32x2 dual-FMA (packed path ptxas won't auto-fuse from C++)
// ---------------------------------------------------------------------------
__device__ __forceinline__ ull ffma2(ull a, ull b, ull c) {
    ull d;
    asm("fma.rn.f32x2 %0, %1, %2, %3;" : "=l"(d) : "l"(a), "l"(b), "l"(c));
    return d;
}
__device__ __forceinline__ ull pack2(float lo, float hi) {
    ull d;
    asm("mov.b64 %0, {%1, %2};" : "=l"(d) : "f"(lo), "f"(hi));
    return d;
}
__device__ __forceinline__ float2 unpack2(ull v) {
    float lo, hi;
    asm("mov.b64 {%0, %1}, %2;" : "=f"(lo), "=f"(hi) : "l"(v));
    return make_float2(lo, hi);
}

__device__ __forceinline__ float fast_sigmoid(float x) {
    float e;
    asm("ex2.approx.f32 %0, %1;" : "=f"(e) : "f"(-1.4426950408889634f * x));
    float r;
    asm("rcp.approx.f32 %0, %1;" : "=f"(r) : "f"(1.0f + e));
    return r;
}
__device__ __forceinline__ float fast_tanh(float x) {
    return fmaf(2.0f, fast_sigmoid(2.0f * x), -1.0f);
}

// ---------------------------------------------------------------------------
// Weight prep: g_W4[(row*4+q)*64+h].component[f] = W_l[gate q, h][ j=jb*4+f ]
// ---------------------------------------------------------------------------
__global__ void prep_weights(const float* __restrict__ Wih0, const float* __restrict__ Whh0,
                             const float* __restrict__ Wih1, const float* __restrict__ Whh1,
                             const float* __restrict__ Wih2, const float* __restrict__ Whh2) {
    int idx = blockIdx.x * blockDim.x + threadIdx.x;
    const int total = NROWS * 4 * 64 * 4;
    if (idx >= total) return;
    int f   = idx & 3;
    int h   = (idx >> 2) & 63;
    int q   = (idx >> 8) & 3;
    int row = idx >> 10;
    int l   = row >> 5;
    int jb  = row & 31;
    int j   = jb * 4 + f;
    int g   = q * 64 + h;
    float val = 0.0f;
    if (l == 0) {
        if (j < 8)       val = Wih0[g * 8 + j];
        else if (j < 72) val = Whh0[g * 64 + (j - 8)];
    } else if (l == 1) {
        val = (j < 64) ? Wih1[g * 64 + j] : Whh1[g * 64 + (j - 64)];
    } else if (l == 2) {
        val = (j < 64) ? Wih2[g * 64 + j] : Whh2[g * 64 + (j - 64)];
    } // pad rows -> 0
    reinterpret_cast<float*>(g_W4)[idx] = val;
}

// ---------------------------------------------------------------------------
// Accumulate NBLK 4-j blocks into acc[gate][b], b in 0..7 (f32x2 lanes sum
// even/odd j). Weights: 4x LDG.128 per block with one-block prefetch
// (pad rows protect the overrun). Activations: warp-uniform LDS.128.
// ---------------------------------------------------------------------------
template <int NBLK, int STRIDE>
__device__ __forceinline__ void accum_part(ull acc[4][8], const float4* __restrict__ wp,
                                           const float* __restrict__ sbase) {
    float4 w0 = __ldg(wp + 0);
    float4 w1 = __ldg(wp + 64);
    float4 w2 = __ldg(wp + 128);
    float4 w3 = __ldg(wp + 192);
#pragma unroll 2
    for (int blk = 0; blk < NBLK; blk++) {
        const float4* np = wp + (blk + 1) * 256;
        float4 n0 = __ldg(np + 0);
        float4 n1 = __ldg(np + 64);
        float4 n2 = __ldg(np + 128);
        float4 n3 = __ldg(np + 192);

        ulonglong2 u0 = *reinterpret_cast<const ulonglong2*>(&w0);
        ulonglong2 u1 = *reinterpret_cast<const ulonglong2*>(&w1);
        ulonglong2 u2 = *reinterpret_cast<const ulonglong2*>(&w2);
        ulonglong2 u3 = *reinterpret_cast<const ulonglong2*>(&w3);
        const float* sp = sbase + blk * 4;
#pragma unroll
        for (int b = 0; b < 8; b++) {
            ulonglong2 a = *reinterpret_cast<const ulonglong2*>(sp + b * STRIDE);
            acc[0][b] = ffma2(u0.x, a.x, acc[0][b]);
            acc[1][b] = ffma2(u1.x, a.x, acc[1][b]);
            acc[2][b] = ffma2(u2.x, a.x, acc[2][b]);
            acc[3][b] = ffma2(u3.x, a.x, acc[3][b]);
            acc[0][b] = ffma2(u0.y, a.y, acc[0][b]);
            acc[1][b] = ffma2(u1.y, a.y, acc[1][b]);
            acc[2][b] = ffma2(u2.y, a.y, acc[2][b]);
            acc[3][b] = ffma2(u3.y, a.y, acc[3][b]);
        }
        w0 = n0; w1 = n1; w2 = n2; w3 = n3;
    }
}

// Dynamic SMEM layout (exceeds 48KB static limit)
struct Smem {
    float hbuf[3][2][BT][HH];   // double-buffered hidden state (48 KB)
    float x_s[2][BT][XDIM];     // double-buffered step input
    float z_s[BT];
    float vf_s[BT];
    float rvf_s[BT];
    float wm_s[HH];
    float wa_s[HH];
    float bm_ba[2];
};

// One 3-layer step with double-buffered hidden state (1 bar per layer).
// Reads hb[l][pp] (prev step), writes hb[l][pp^1].
__device__ __forceinline__ void step3(float (&c)[3][8], const float (&bias)[3][4],
                                      int h, int bs, int pp,
                                      float (*hb)[2][BT][HH],
                                      const float (*x_s)[XDIM]) {
#pragma unroll
    for (int l = 0; l < 3; l++) {
        ull acc[4][8];
#pragma unroll
        for (int q = 0; q < 4; q++)
#pragma unroll
            for (int k = 0; k < 8; k++) acc[q][k] = pack2(bias[l][q], 0.0f);

        if (l == 0) {
            accum_part<2,  XDIM>(acc, g_W4 + 0 * 256 + h,  &x_s[bs][0]);
            accum_part<16, HH  >(acc, g_W4 + 2 * 256 + h,  &hb[0][pp][bs][0]);
        } else if (l == 1) {
            accum_part<16, HH  >(acc, g_W4 + 32 * 256 + h, &hb[0][pp ^ 1][bs][0]);
            accum_part<16, HH  >(acc, g_W4 + 48 * 256 + h, &hb[1][pp][bs][0]);
        } else {
            accum_part<16, HH  >(acc, g_W4 + 64 * 256 + h, &hb[1][pp ^ 1][bs][0]);
            accum_part<16, HH  >(acc, g_W4 + 80 * 256 + h, &hb[2][pp][bs][0]);
        }

        float hv[8];
#pragma unroll
        for (int k = 0; k < 8; k++) {
            float2 xi2 = unpack2(acc[0][k]);
            float2 xf2 = unpack2(acc[1][k]);
            float2 xg2 = unpack2(acc[2][k]);
            float2 xo2 = unpack2(acc[3][k]);
            float iv = fast_sigmoid(xi2.x + xi2.y);
            float fv = fast_sigmoid(xf2.x + xf2.y);
            float gv = fast_tanh(xg2.x + xg2.y);
            float ov = fast_sigmoid(xo2.x + xo2.y);
            float cn = fmaf(fv, c[l][k], iv * gv);
            c[l][k]  = cn;
            hv[k]    = ov * fast_tanh(cn);
        }
#pragma unroll
        for (int k = 0; k < 8; k++) hb[l][pp ^ 1][bs + k][h] = hv[k];
        __syncthreads();   // layer-l outputs visible; old buffer free
    }
}

// ---------------------------------------------------------------------------
// Main kernel: one CTA per 32-batch tile, whole encoder+decoder sequence.
// ---------------------------------------------------------------------------
__global__ void __launch_bounds__(NTHR, 1)
lstm_seq_kernel(const float* __restrict__ enc_x, const float* __restrict__ enc_z,
                const float* __restrict__ dec_x, const float* __restrict__ v,
                const float* __restrict__ eps,
                const float* __restrict__ b0, const float* __restrict__ b1,
                const float* __restrict__ b2,
                const float* __restrict__ w_m, const float* __restrict__ b_m,
                const float* __restrict__ w_a, const float* __restrict__ b_a,
                float* __restrict__ out) {
    extern __shared__ __align__(16) char smem_raw[];
    Smem& sm = *reinterpret_cast<Smem*>(smem_raw);

    const int t   = threadIdx.x;
    const int h   = t & 63;
    const int bs  = (t >> 6) * 8;    // 4 groups x 8 batches = 32
    const int b0g = blockIdx.x * BT;

    float bias[3][4];
#pragma unroll
    for (int q = 0; q < 4; q++) {
        bias[0][q] = b0[q * 64 + h];
        bias[1][q] = b1[q * 64 + h];
        bias[2][q] = b2[q * 64 + h];
    }

    for (int i = t; i < 3 * 2 * BT * HH; i += NTHR) (&sm.hbuf[0][0][0][0])[i] = 0.0f;
    if (t < HH) { sm.wm_s[t] = w_m[t]; sm.wa_s[t] = w_a[t]; }
    if (t == 0) { sm.bm_ba[0] = b_m[0]; sm.bm_ba[1] = b_a[0]; }

    float c[3][8];
#pragma unroll
    for (int l = 0; l < 3; l++)
#pragma unroll
        for (int k = 0; k < 8; k++) c[l][k] = 0.0f;

    const int bb = t >> 3, xi = t & 7;   // 256 threads = 32x8 x-loader
    int pp = 0;

    // ---------------- encoder ----------------
    // x double-buffered: load step s+1 under cover of step s's layer barriers.
    sm.x_s[0][bb][xi] = enc_x[(size_t)(b0g + bb) * (TE * XDIM) + 0 * XDIM + xi];
    __syncthreads();
    for (int s = 0; s < TE; s++) {
        int cur = s & 1;
        if (s + 1 < TE)
            sm.x_s[cur ^ 1][bb][xi] =
                enc_x[(size_t)(b0g + bb) * (TE * XDIM) + (s + 1) * XDIM + xi];
        step3(c, bias, h, bs, pp, sm.hbuf, sm.x_s[cur]);
        pp ^= 1;
    }

    // ---------------- decoder init ----------------
    if (t < BT) {
        float vf  = v[b0g + t];
        float rvf = 1.0f / vf;
        sm.vf_s[t]  = vf;
        sm.rvf_s[t] = rvf;
        sm.z_s[t]   = enc_z[(size_t)(b0g + t) * TE + (TE - 1)] * rvf;
    }
    __syncthreads();

    // ---------------- decoder ----------------
    for (int s = 0; s < TD; s++) {
        {
            float xv;
            if (xi == 0) xv = sm.z_s[bb];
            else xv = dec_x[(size_t)(b0g + bb) * (TD * (XDIM - 1)) + s * (XDIM - 1) + (xi - 1)];
            sm.x_s[0][bb][xi] = xv;
        }
        __syncthreads();

        step3(c, bias, h, bs, pp, sm.hbuf, sm.x_s[0]);

        if (t < BT) {
            float m  = sm.bm_ba[0];
            float ap = sm.bm_ba[1];
            const float* hrow = &sm.hbuf[2][pp ^ 1][t][0];
#pragma unroll
            for (int kk = 0; kk < HH; kk++) {
                int k = (kk + t) & 63;       // bank-conflict-free rotation
                float hv = hrow[k];
                m  = fmaf(hv, sm.wm_s[k], m);
                ap = fmaf(hv, sm.wa_s[k], ap);
            }
            float vf = sm.vf_s[t];
            m *= vf;
            float sp = fmaxf(ap, 0.0f) + log1pf(__expf(-fabsf(ap)));
            float a  = sp * vf;
            float zs = fmaf(a, eps[(size_t)(b0g + t) * TD + s], m);
            out[(size_t)(b0g + t) * TD + s] = zs;
            sm.z_s[t] = zs * sm.rvf_s[t];
        }
        pp ^= 1;
        __syncthreads();   // z_s ready before next step's loader reads it
    }
}

// ---------------------------------------------------------------------------
// Input order: enc_x, enc_z, dec_x, v, eps,
//   W_ih0, W_hh0, b0, W_ih1, W_hh1, b1, W_ih2, W_hh2, b2, w_m, b_m, w_a, b_a
// ---------------------------------------------------------------------------
extern "C" void kernel_launch(void* const* d_in, const int* in_sizes, int n_in,
                              void* d_out, int out_size) {
    (void)in_sizes; (void)n_in; (void)out_size;
    const float* enc_x = (const float*)d_in[0];
    const float* enc_z = (const float*)d_in[1];
    const float* dec_x = (const float*)d_in[2];
    const float* v     = (const float*)d_in[3];
    const float* eps   = (const float*)d_in[4];
    const float* Wih0  = (const float*)d_in[5];
    const float* Whh0  = (const float*)d_in[6];
    const float* b0    = (const float*)d_in[7];
    const float* Wih1  = (const float*)d_in[8];
    const float* Whh1  = (const float*)d_in[9];
    const float* b1    = (const float*)d_in[10];
    const float* Wih2  = (const float*)d_in[11];
    const float* Whh2  = (const float*)d_in[12];
    const float* b2    = (const float*)d_in[13];
    const float* w_m   = (const float*)d_in[14];
    const float* b_m   = (const float*)d_in[15];
    const float* w_a   = (const float*)d_in[16];
    const float* b_a   = (const float*)d_in[17];
    float* out = (float*)d_out;

    // >48KB smem: opt in every call (idempotent, not a stream op — capture-safe)
    cudaFuncSetAttribute(lstm_seq_kernel,
                         cudaFuncAttributeMaxDynamicSharedMemorySize,
                         (int)sizeof(Smem));

    const int total = NROWS * 4 * 64 * 4;
    prep_weights<<<(total + 255) / 256, 256>>>(Wih0, Whh0, Wih1, Whh1, Wih2, Whh2);
    lstm_seq_kernel<<<BTOT / BT, NTHR, sizeof(Smem)>>>(enc_x, enc_z, dec_x, v, eps,
                                                       b0, b1, b2, w_m, b_m, w_a, b_a, out);
}